// round 8
// baseline (speedup 1.0000x reference)
#include <cuda_runtime.h>
#include <cuda_bf16.h>

// HybridQLSTM_65481071409480 — GB300 (sm_103a)
//
// Algebraic collapse (verified on-HW, rel_err = 0.0 exactly):
//   log_softmax over a broadcast-constant row of length T=50 is identically
//   -log(50) for every output element, independent of ALL inputs. The whole
//   embedding/LSTM/sin pipeline is dead code. Output = fill of fp32 -log(50)
//   over 819200 floats (3.125 MiB).
//
// History: 800x256 one-float4-store configs pin total dur at exactly 4.608us
// (timer quantum 0.032us); body tweaks are invisible -> launch/replay floor.
// R8 probe: Blackwell 256-bit stores (st.global.v8.f32 -> STG.E.256) halve
// thread count AND store count: 400 CTAs x 256 thr x one 32B store. Fewer
// CTA dispatches with unchanged per-thread serial work — the one remaining
// structural reduction. Generic float4 kernel kept as fallback for sizes
// that don't fit 8-wide exactly.

__global__ __launch_bounds__(256)
void fill_neglog50_v8(float* __restrict__ out) {
    const float v = -3.9120230674743652f;  // fp32-nearest -log(50)
    const int idx = blockIdx.x * blockDim.x + threadIdx.x;
    float* p = out + (size_t)idx * 8;      // 32B-aligned (base is 256B-aligned)
    asm volatile(
        "st.global.v8.f32 [%0], {%1, %2, %3, %4, %5, %6, %7, %8};"
        :: "l"(p), "f"(v), "f"(v), "f"(v), "f"(v),
                   "f"(v), "f"(v), "f"(v), "f"(v)
        : "memory");
}

__global__ __launch_bounds__(256)
void fill_neglog50_generic(float4* __restrict__ out4, int n4,
                           float* __restrict__ out_tail, int n_tail) {
    const float v = -3.9120230674743652f;
    const int idx = blockIdx.x * blockDim.x + threadIdx.x;
    if (idx < n4) {
        out4[idx] = make_float4(v, v, v, v);
    }
    if (idx < n_tail) {
        out_tail[idx] = v;
    }
}

extern "C" void kernel_launch(void* const* d_in, const int* in_sizes, int n_in,
                              void* d_out, int out_size) {
    (void)d_in; (void)in_sizes; (void)n_in;
    if (out_size <= 0) return;

    float* out = (float*)d_out;
    const int threads = 256;
    int n8 = out_size >> 3;            // 102400 for this problem

    if ((out_size & 7) == 0 && n8 > 0 && (n8 % threads) == 0) {
        // Exact fit: 400 CTAs x 256 threads, one unguarded STG.E.256 each.
        fill_neglog50_v8<<<n8 / threads, threads>>>(out);
    } else {
        int n4 = out_size >> 2;
        int n_tail = out_size & 3;
        float* tail_ptr = out + (size_t)n4 * 4;
        int blocks = (n4 + threads - 1) / threads;
        if (blocks < 1) blocks = 1;
        fill_neglog50_generic<<<blocks, threads>>>(
            (float4*)out, n4, tail_ptr, n_tail);
    }
}

// round 10
// speedup vs baseline: 1.4759x; 1.4759x over previous
#include <cuda_runtime.h>
#include <cuda_bf16.h>

// HybridQLSTM_65481071409480 — GB300 (sm_103a) — FINAL (resubmit; R9 was a
// GPU-acquisition timeout, kernel never ran)
//
// Algebraic collapse (verified on-HW across 6 passing rounds, rel_err = 0.0
// exactly): the reference ends with
//     log_softmax(broadcast_to(expectation[..., None], (S,B,T)), axis=-1)
// over a CONSTANT row of length T=50, which is identically -log(50) for
// every element, independent of ALL inputs (stabilized log_softmax computes
// 0 - log(sum exp 0) = -log 50 bit-exactly in fp32). The embedding gather,
// 512-step LSTM scan, and sin() expectation are dead code. The kernel is a
// 3.125 MiB constant fill of fp32 -log(50).
//
// Convergence evidence (7 measured configs): in-kernel time pinned at
// ~3.5-3.8us (= T_ovh + CTA ramp; DRAM=0%, writes absorbed by L2; store
// drain ~0.3us) for every shape; total dur_us bimodal 4.6/6.6 across
// container instances independent of kernel shape. Best on both metrics:
// 800 CTAs x 256 threads, one guarded float4 store per thread
// (kernel 3.488us, total 4.608us). This is that kernel, terminal.

__global__ __launch_bounds__(256)
void fill_neglog50_kernel(float4* __restrict__ out4, int n4,
                          float* __restrict__ out_tail, int n_tail) {
    const float v = -3.9120230674743652f;  // fp32-nearest -log(50)
    const int idx = blockIdx.x * blockDim.x + threadIdx.x;
    if (idx < n4) {
        out4[idx] = make_float4(v, v, v, v);
    }
    if (idx < n_tail) {                    // n_tail = 0 for this problem
        out_tail[idx] = v;
    }
}

extern "C" void kernel_launch(void* const* d_in, const int* in_sizes, int n_in,
                              void* d_out, int out_size) {
    (void)d_in; (void)in_sizes; (void)n_in;
    if (out_size <= 0) return;

    float* out = (float*)d_out;
    int n4 = out_size >> 2;            // 204800
    int n_tail = out_size & 3;         // 0
    float* tail_ptr = out + (size_t)n4 * 4;

    const int threads = 256;
    int blocks = (n4 + threads - 1) / threads;  // 800
    if (blocks < 1) blocks = 1;

    fill_neglog50_kernel<<<blocks, threads>>>(
        (float4*)out, n4, tail_ptr, n_tail);
}